// round 13
// baseline (speedup 1.0000x reference)
#include <cuda_runtime.h>
#include <cuda_bf16.h>
#include <math.h>

#define N 8192
#define KD 32
#define STRIP 16
#define NSTRIPS (N / STRIP)     // 512

#define MUVAL (1.0f / 8192.0f)
#define NUVAL (1.0f / 8192.0f)

// Scratch (allocation-free: device globals)
__device__ __nv_bfloat16 d_K[(size_t)N * N];      // 128 MB: K = exp(-C) bf16
__device__ float d_v[N];                           // v = exp(g)
__device__ float d_ps[(size_t)NSTRIPS * N];        // column-sum partials (16 MB)
__device__ float d_pt[(size_t)NSTRIPS * N];        // loss partials (final iter)

__device__ __forceinline__ unsigned tf32cvt(float v)
{
    unsigned r;
    asm("cvt.rna.tf32.f32 %0, %1;" : "=r"(r) : "f"(v));
    return r;
}

__device__ __forceinline__ void mma_tf32(
    float& d0, float& d1, float& d2, float& d3,
    unsigned a0, unsigned a1, unsigned a2, unsigned a3,
    unsigned b0, unsigned b1)
{
    asm("mma.sync.aligned.m16n8k8.row.col.f32.tf32.tf32.f32 "
        "{%0,%1,%2,%3}, {%4,%5,%6,%7}, {%8,%9}, {%0,%1,%2,%3};"
        : "+f"(d0), "+f"(d1), "+f"(d2), "+f"(d3)
        : "r"(a0), "r"(a1), "r"(a2), "r"(a3), "r"(b0), "r"(b1));
}

// ---------------------------------------------------------------------------
// Kernel 1: build K = exp(-(|x_i|^2 + |y_j|^2 - 2 x_i.y_j)) in bf16 via
// tf32 tensor-core MMA for the dot products. 128x128 tile per block, 8 warps,
// warp w owns m-rows [16w, 16w+16), 16 n-tiles of 8, K=32 -> 4 k-steps.
// Also inits v = 1 and zeroes the output scalar.
// ---------------------------------------------------------------------------
__global__ __launch_bounds__(256) void build_k_kernel(
    const float* __restrict__ x, const float* __restrict__ y,
    float* __restrict__ out)
{
    __shared__ float xs[128][36];   // pad 36: (4r+c)%32 distinct -> conflict-free frags
    __shared__ float ys[128][36];
    __shared__ float xn[128];
    __shared__ float yn[128];

    const int tid = threadIdx.x;
    const int lane = tid & 31;
    const int w = tid >> 5;          // warp 0..7
    const int bx = blockIdx.x, by = blockIdx.y;
    const int row0 = by * 128, col0 = bx * 128;

    {
        int gid = (by * gridDim.x + bx) * 256 + tid;
        if (gid < N) d_v[gid] = 1.0f;
        if (gid == 0) out[0] = 0.0f;
    }

    // stage tiles (row-major, padded)
    const float4* x4 = (const float4*)(x + (size_t)row0 * KD);
    const float4* y4 = (const float4*)(y + (size_t)col0 * KD);
#pragma unroll
    for (int it = 0; it < 4; ++it) {
        int f = tid + it * 256;          // 0..1023
        int r = f >> 3;
        int c = (f & 7) * 4;
        float4 vx = x4[f];
        xs[r][c] = vx.x; xs[r][c + 1] = vx.y; xs[r][c + 2] = vx.z; xs[r][c + 3] = vx.w;
        float4 vy = y4[f];
        ys[r][c] = vy.x; ys[r][c + 1] = vy.y; ys[r][c + 2] = vy.z; ys[r][c + 3] = vy.w;
    }
    __syncthreads();

    // squared norms (fp32, from staged tiles)
    if (tid < 128) {
        float s = 0.0f;
#pragma unroll
        for (int k = 0; k < KD; ++k) { float a = xs[tid][k]; s = fmaf(a, a, s); }
        xn[tid] = s;
    } else {
        int r = tid - 128;
        float s = 0.0f;
#pragma unroll
        for (int k = 0; k < KD; ++k) { float a = ys[r][k]; s = fmaf(a, a, s); }
        yn[r] = s;
    }
    __syncthreads();

    const int g = lane >> 2;         // 0..7
    const int tg = lane & 3;         // 0..3
    const int ra = 16 * w + g;       // A-frag row (local)
    const int rb = ra + 8;

    // A fragments for all 4 k-steps (16 regs)
    unsigned A[4][4];
#pragma unroll
    for (int k8 = 0; k8 < 4; ++k8) {
        A[k8][0] = tf32cvt(xs[ra][k8 * 8 + tg]);
        A[k8][1] = tf32cvt(xs[rb][k8 * 8 + tg]);
        A[k8][2] = tf32cvt(xs[ra][k8 * 8 + tg + 4]);
        A[k8][3] = tf32cvt(xs[rb][k8 * 8 + tg + 4]);
    }

    float acc[16][4];
#pragma unroll
    for (int n = 0; n < 16; ++n)
#pragma unroll
        for (int q = 0; q < 4; ++q) acc[n][q] = 0.0f;

#pragma unroll
    for (int n = 0; n < 16; ++n) {
        const int yr = n * 8 + g;    // B col(n) index
#pragma unroll
        for (int k8 = 0; k8 < 4; ++k8) {
            unsigned b0 = tf32cvt(ys[yr][k8 * 8 + tg]);
            unsigned b1 = tf32cvt(ys[yr][k8 * 8 + tg + 4]);
            mma_tf32(acc[n][0], acc[n][1], acc[n][2], acc[n][3],
                     A[k8][0], A[k8][1], A[k8][2], A[k8][3], b0, b1);
        }
    }

    // epilogue: K = exp(2*dot - xn - yn), bf16x2 stores
    const float xna = xn[ra];
    const float xnb = xn[rb];
    const int gra = row0 + ra;
    const int grb = row0 + rb;
#pragma unroll
    for (int n = 0; n < 16; ++n) {
        int c0 = n * 8 + 2 * tg;         // local col (even)
        float yn0 = yn[c0], yn1 = yn[c0 + 1];
        float k00 = __expf(2.0f * acc[n][0] - xna - yn0);
        float k01 = __expf(2.0f * acc[n][1] - xna - yn1);
        float k10 = __expf(2.0f * acc[n][2] - xnb - yn0);
        float k11 = __expf(2.0f * acc[n][3] - xnb - yn1);
        *(__nv_bfloat162*)(d_K + (size_t)gra * N + col0 + c0) = __floats2bfloat162_rn(k00, k01);
        *(__nv_bfloat162*)(d_K + (size_t)grb * N + col0 + c0) = __floats2bfloat162_rn(k10, k11);
    }
}

// ---------------------------------------------------------------------------
// Kernel 2 (fused sweep): block owns a 16-row strip of K.
//   Phase 1: u_i = MU / sum_j K_ij v_j     (strip from DRAM; 1 warp / row)
//   Phase 2: ps[strip][j] = sum_i K_ij u_i (strip re-read, hits L2)
// grid NSTRIPS=512, block 512, 2 blocks/SM -> phases of co-resident blocks
// overlap (one streams DRAM while the other re-reads L2). Resident set
// 2 x 256KB x 148 = 74 MB < L2.
// FIN: also t-partials sum_i (-log K) K u for the loss.
// ---------------------------------------------------------------------------
template <bool FIN>
__global__ __launch_bounds__(512, 2) void sweep_kernel()
{
    __shared__ float us[STRIP];

    const int tid = threadIdx.x;
    const int wrp = tid >> 5;            // 0..15
    const int lane = tid & 31;
    const int i0 = blockIdx.x * STRIP;

    const uint4*  K8 = (const uint4*)d_K;   // 1024 uint4 per row
    const float4* v4 = (const float4*)d_v;

    // ---- Phase 1: warp w handles row i0+w ----
    {
        const int r0 = i0 + wrp;
        const uint4* Kr = K8 + (size_t)r0 * (N / 8);
        float a0 = 0.0f;
#pragma unroll 8
        for (int it = 0; it < 32; ++it) {
            int idx = lane + it * 32;                 // uint4 col index
            float4 va = v4[2 * idx];
            float4 vb = v4[2 * idx + 1];
            union { uint4 u; __nv_bfloat162 h[4]; } k0;
            k0.u = Kr[idx];
            float2 c;
            c = __bfloat1622float2(k0.h[0]); a0 = fmaf(c.x, va.x, a0); a0 = fmaf(c.y, va.y, a0);
            c = __bfloat1622float2(k0.h[1]); a0 = fmaf(c.x, va.z, a0); a0 = fmaf(c.y, va.w, a0);
            c = __bfloat1622float2(k0.h[2]); a0 = fmaf(c.x, vb.x, a0); a0 = fmaf(c.y, vb.y, a0);
            c = __bfloat1622float2(k0.h[3]); a0 = fmaf(c.x, vb.z, a0); a0 = fmaf(c.y, vb.w, a0);
        }
#pragma unroll
        for (int o = 16; o > 0; o >>= 1)
            a0 += __shfl_xor_sync(0xffffffffu, a0, o);
        if (lane == 0) us[wrp] = MUVAL / a0;
    }
    __syncthreads();

    // ---- Phase 2: column partials; 2 uint4-cols / thread (sequential halves) ----
#pragma unroll
    for (int half = 0; half < 2; ++half) {
        const int j4 = tid + half * 512;             // uint4 col index 0..1023
        float acc[8];
        float tac[8];
#pragma unroll
        for (int c = 0; c < 8; ++c) { acc[c] = 0.0f; tac[c] = 0.0f; }

#pragma unroll 4
        for (int r = 0; r < STRIP; ++r) {
            union { uint4 u; __nv_bfloat162 h[4]; } k;
            k.u = K8[(size_t)(i0 + r) * (N / 8) + j4];
            float ur = us[r];
            float c[8];
            float2 t0 = __bfloat1622float2(k.h[0]);
            float2 t1 = __bfloat1622float2(k.h[1]);
            float2 t2 = __bfloat1622float2(k.h[2]);
            float2 t3 = __bfloat1622float2(k.h[3]);
            c[0] = t0.x; c[1] = t0.y; c[2] = t1.x; c[3] = t1.y;
            c[4] = t2.x; c[5] = t2.y; c[6] = t3.x; c[7] = t3.y;
#pragma unroll
            for (int j = 0; j < 8; ++j) {
                acc[j] = fmaf(c[j], ur, acc[j]);
                if (FIN) {
                    float kj = c[j];
                    tac[j] += (kj > 0.0f) ? (-__logf(kj)) * kj * ur : 0.0f;
                }
            }
        }

        float4* ps4 = (float4*)&d_ps[(size_t)blockIdx.x * N + (size_t)j4 * 8];
        float4 o0, o1;
        o0.x = acc[0]; o0.y = acc[1]; o0.z = acc[2]; o0.w = acc[3];
        o1.x = acc[4]; o1.y = acc[5]; o1.z = acc[6]; o1.w = acc[7];
        ps4[0] = o0; ps4[1] = o1;
        if (FIN) {
            float4* pt4 = (float4*)&d_pt[(size_t)blockIdx.x * N + (size_t)j4 * 8];
            float4 p0, p1;
            p0.x = tac[0]; p0.y = tac[1]; p0.z = tac[2]; p0.w = tac[3];
            p1.x = tac[4]; p1.y = tac[5]; p1.z = tac[6]; p1.w = tac[7];
            pt4[0] = p0; pt4[1] = p1;
        }
    }
}

// ---------------------------------------------------------------------------
// Kernel 3: combine 512 strip partials -> v_j = NU / colsum_j.
// 4 threads per column (128 strips each) + smem reduce.
// grid 128, block 256 (64 columns per block).
// ---------------------------------------------------------------------------
__global__ __launch_bounds__(256) void v_combine_kernel()
{
    __shared__ float sm[4][64];
    const int tid = threadIdx.x;
    const int cl = tid & 63;
    const int g = tid >> 6;                       // 0..3
    const int j = blockIdx.x * 64 + cl;

    float s = 0.0f;
#pragma unroll 8
    for (int k = 0; k < 128; ++k)
        s += d_ps[(size_t)(g * 128 + k) * N + j];
    sm[g][cl] = s;
    __syncthreads();
    if (tid < 64) {
        float tot = sm[0][tid] + sm[1][tid] + sm[2][tid] + sm[3][tid];
        d_v[blockIdx.x * 64 + tid] = NUVAL / tot;
    }
}

// Final combine: also loss = sum_j v_j * t_j.
__global__ __launch_bounds__(256) void v_combine_final_kernel(float* __restrict__ out)
{
    __shared__ float sm[4][64];
    __shared__ float smt[4][64];
    __shared__ float reds[2];
    const int tid = threadIdx.x;
    const int cl = tid & 63;
    const int g = tid >> 6;
    const int j = blockIdx.x * 64 + cl;

    float s = 0.0f, t = 0.0f;
#pragma unroll 8
    for (int k = 0; k < 128; ++k) {
        s += d_ps[(size_t)(g * 128 + k) * N + j];
        t += d_pt[(size_t)(g * 128 + k) * N + j];
    }
    sm[g][cl] = s;
    smt[g][cl] = t;
    __syncthreads();
    if (tid < 64) {
        float tot = sm[0][tid] + sm[1][tid] + sm[2][tid] + sm[3][tid];
        float tt  = smt[0][tid] + smt[1][tid] + smt[2][tid] + smt[3][tid];
        float lp = (NUVAL / tot) * tt;
#pragma unroll
        for (int o = 16; o > 0; o >>= 1) lp += __shfl_xor_sync(0xffffffffu, lp, o);
        if ((tid & 31) == 0) reds[tid >> 5] = lp;
    }
    __syncthreads();
    if (tid == 0) atomicAdd(out, reds[0] + reds[1]);
}

// ---------------------------------------------------------------------------
extern "C" void kernel_launch(void* const* d_in, const int* in_sizes, int n_in,
                              void* d_out, int out_size)
{
    const float* x = (const float*)d_in[0];
    const float* y = (const float*)d_in[1];
    float* out = (float*)d_out;

    build_k_kernel<<<dim3(64, 64), 256>>>(x, y, out);

    for (int t = 0; t < 10; ++t) {
        if (t < 9) {
            sweep_kernel<false><<<NSTRIPS, 512>>>();
            v_combine_kernel<<<N / 64, 256>>>();
        } else {
            sweep_kernel<true><<<NSTRIPS, 512>>>();
            v_combine_final_kernel<<<N / 64, 256>>>(out);
        }
    }
}

// round 15
// speedup vs baseline: 1.2302x; 1.2302x over previous
#include <cuda_runtime.h>
#include <cuda_bf16.h>
#include <math.h>

#define N 8192
#define KD 32
#define STRIP 32
#define NSTRIPS (N / STRIP)     // 256

#define MUVAL (1.0f / 8192.0f)
#define NUVAL (1.0f / 8192.0f)

// Scratch (allocation-free: device globals)
__device__ __nv_bfloat16 d_K[(size_t)N * N];      // 128 MB: K = exp(-C) bf16
__device__ float d_v[N];                           // v = exp(g)
__device__ float d_ps[(size_t)NSTRIPS * N];        // column-sum partials (8 MB)
__device__ float d_pt[(size_t)NSTRIPS * N];        // loss partials (final iter)

__device__ __forceinline__ unsigned tf32cvt(float v)
{
    unsigned r;
    asm("cvt.rna.tf32.f32 %0, %1;" : "=r"(r) : "f"(v));
    return r;
}

__device__ __forceinline__ void mma_tf32(
    float& d0, float& d1, float& d2, float& d3,
    unsigned a0, unsigned a1, unsigned a2, unsigned a3,
    unsigned b0, unsigned b1)
{
    asm("mma.sync.aligned.m16n8k8.row.col.f32.tf32.tf32.f32 "
        "{%0,%1,%2,%3}, {%4,%5,%6,%7}, {%8,%9}, {%0,%1,%2,%3};"
        : "+f"(d0), "+f"(d1), "+f"(d2), "+f"(d3)
        : "r"(a0), "r"(a1), "r"(a2), "r"(a3), "r"(b0), "r"(b1));
}

// ---------------------------------------------------------------------------
// Kernel 1: build K = exp(-(|x_i|^2 + |y_j|^2 - 2 x_i.y_j)) in bf16 via
// tf32 tensor-core MMA. 128x128 tile per block, 8 warps.
// Also inits v = 1 and zeroes the output scalar.
// ---------------------------------------------------------------------------
__global__ __launch_bounds__(256) void build_k_kernel(
    const float* __restrict__ x, const float* __restrict__ y,
    float* __restrict__ out)
{
    __shared__ float xs[128][36];
    __shared__ float ys[128][36];
    __shared__ float xn[128];
    __shared__ float yn[128];

    const int tid = threadIdx.x;
    const int lane = tid & 31;
    const int w = tid >> 5;          // warp 0..7
    const int bx = blockIdx.x, by = blockIdx.y;
    const int row0 = by * 128, col0 = bx * 128;

    {
        int gid = (by * gridDim.x + bx) * 256 + tid;
        if (gid < N) d_v[gid] = 1.0f;
        if (gid == 0) out[0] = 0.0f;
    }

    const float4* x4 = (const float4*)(x + (size_t)row0 * KD);
    const float4* y4 = (const float4*)(y + (size_t)col0 * KD);
#pragma unroll
    for (int it = 0; it < 4; ++it) {
        int f = tid + it * 256;          // 0..1023
        int r = f >> 3;
        int c = (f & 7) * 4;
        float4 vx = x4[f];
        xs[r][c] = vx.x; xs[r][c + 1] = vx.y; xs[r][c + 2] = vx.z; xs[r][c + 3] = vx.w;
        float4 vy = y4[f];
        ys[r][c] = vy.x; ys[r][c + 1] = vy.y; ys[r][c + 2] = vy.z; ys[r][c + 3] = vy.w;
    }
    __syncthreads();

    if (tid < 128) {
        float s = 0.0f;
#pragma unroll
        for (int k = 0; k < KD; ++k) { float a = xs[tid][k]; s = fmaf(a, a, s); }
        xn[tid] = s;
    } else {
        int r = tid - 128;
        float s = 0.0f;
#pragma unroll
        for (int k = 0; k < KD; ++k) { float a = ys[r][k]; s = fmaf(a, a, s); }
        yn[r] = s;
    }
    __syncthreads();

    const int g = lane >> 2;         // 0..7
    const int tg = lane & 3;         // 0..3
    const int ra = 16 * w + g;       // A-frag row (local)
    const int rb = ra + 8;

    unsigned A[4][4];
#pragma unroll
    for (int k8 = 0; k8 < 4; ++k8) {
        A[k8][0] = tf32cvt(xs[ra][k8 * 8 + tg]);
        A[k8][1] = tf32cvt(xs[rb][k8 * 8 + tg]);
        A[k8][2] = tf32cvt(xs[ra][k8 * 8 + tg + 4]);
        A[k8][3] = tf32cvt(xs[rb][k8 * 8 + tg + 4]);
    }

    float acc[16][4];
#pragma unroll
    for (int n = 0; n < 16; ++n)
#pragma unroll
        for (int q = 0; q < 4; ++q) acc[n][q] = 0.0f;

#pragma unroll
    for (int n = 0; n < 16; ++n) {
        const int yr = n * 8 + g;
#pragma unroll
        for (int k8 = 0; k8 < 4; ++k8) {
            unsigned b0 = tf32cvt(ys[yr][k8 * 8 + tg]);
            unsigned b1 = tf32cvt(ys[yr][k8 * 8 + tg + 4]);
            mma_tf32(acc[n][0], acc[n][1], acc[n][2], acc[n][3],
                     A[k8][0], A[k8][1], A[k8][2], A[k8][3], b0, b1);
        }
    }

    const float xna = xn[ra];
    const float xnb = xn[rb];
    const int gra = row0 + ra;
    const int grb = row0 + rb;
#pragma unroll
    for (int n = 0; n < 16; ++n) {
        int c0 = n * 8 + 2 * tg;
        float yn0 = yn[c0], yn1 = yn[c0 + 1];
        float k00 = __expf(2.0f * acc[n][0] - xna - yn0);
        float k01 = __expf(2.0f * acc[n][1] - xna - yn1);
        float k10 = __expf(2.0f * acc[n][2] - xnb - yn0);
        float k11 = __expf(2.0f * acc[n][3] - xnb - yn1);
        *(__nv_bfloat162*)(d_K + (size_t)gra * N + col0 + c0) = __floats2bfloat162_rn(k00, k01);
        *(__nv_bfloat162*)(d_K + (size_t)grb * N + col0 + c0) = __floats2bfloat162_rn(k10, k11);
    }
}

// ---------------------------------------------------------------------------
// Kernel 2 (fused sweep): block owns a 32-row strip of K.
//   Phase 1: u_i = MU / sum_j K_ij v_j     (strip from DRAM; 1 warp / row)
//   Phase 2: ps[strip][j] = sum_i K_ij u_i (strip re-read, hits L2)
// grid NSTRIPS=256, block 1024, 1 block/SM (resident set 74 MB < L2).
// FIN: also t-partials sum_i (-log K) K u for the loss.
// ---------------------------------------------------------------------------
template <bool FIN>
__global__ __launch_bounds__(1024, 1) void sweep_kernel()
{
    __shared__ float us[STRIP];

    const int tid = threadIdx.x;
    const int wrp = tid >> 5;            // 0..31
    const int lane = tid & 31;
    const int i0 = blockIdx.x * STRIP;

    const uint4*  K8 = (const uint4*)d_K;   // 1024 uint4 per row
    const float4* v4 = (const float4*)d_v;

    // ---- Phase 1: warp w handles row i0+w ----
    {
        const int r0 = i0 + wrp;
        const uint4* Kr = K8 + (size_t)r0 * (N / 8);
        float a0 = 0.0f;
#pragma unroll 8
        for (int it = 0; it < 32; ++it) {
            int idx = lane + it * 32;                 // uint4 col index
            float4 va = v4[2 * idx];
            float4 vb = v4[2 * idx + 1];
            union { uint4 u; __nv_bfloat162 h[4]; } k0;
            k0.u = Kr[idx];
            float2 c;
            c = __bfloat1622float2(k0.h[0]); a0 = fmaf(c.x, va.x, a0); a0 = fmaf(c.y, va.y, a0);
            c = __bfloat1622float2(k0.h[1]); a0 = fmaf(c.x, va.z, a0); a0 = fmaf(c.y, va.w, a0);
            c = __bfloat1622float2(k0.h[2]); a0 = fmaf(c.x, vb.x, a0); a0 = fmaf(c.y, vb.y, a0);
            c = __bfloat1622float2(k0.h[3]); a0 = fmaf(c.x, vb.z, a0); a0 = fmaf(c.y, vb.w, a0);
        }
#pragma unroll
        for (int o = 16; o > 0; o >>= 1)
            a0 += __shfl_xor_sync(0xffffffffu, a0, o);
        if (lane == 0) us[wrp] = MUVAL / a0;
    }
    __syncthreads();

    // ---- Phase 2: column partials over the strip; 1 uint4 col / thread ----
    {
        const int j4 = tid;                          // uint4 col index 0..1023
        float acc[8];
        float tac[8];
#pragma unroll
        for (int c = 0; c < 8; ++c) { acc[c] = 0.0f; tac[c] = 0.0f; }

#pragma unroll 4
        for (int r = 0; r < STRIP; ++r) {
            union { uint4 u; __nv_bfloat162 h[4]; } k;
            k.u = K8[(size_t)(i0 + r) * (N / 8) + j4];
            float ur = us[r];
            float c[8];
            float2 t0 = __bfloat1622float2(k.h[0]);
            float2 t1 = __bfloat1622float2(k.h[1]);
            float2 t2 = __bfloat1622float2(k.h[2]);
            float2 t3 = __bfloat1622float2(k.h[3]);
            c[0] = t0.x; c[1] = t0.y; c[2] = t1.x; c[3] = t1.y;
            c[4] = t2.x; c[5] = t2.y; c[6] = t3.x; c[7] = t3.y;
#pragma unroll
            for (int j = 0; j < 8; ++j) {
                acc[j] = fmaf(c[j], ur, acc[j]);
                if (FIN) {
                    float kj = c[j];
                    tac[j] += (kj > 0.0f) ? (-__logf(kj)) * kj * ur : 0.0f;
                }
            }
        }

        float4* ps4 = (float4*)&d_ps[(size_t)blockIdx.x * N + (size_t)j4 * 8];
        float4 o0, o1;
        o0.x = acc[0]; o0.y = acc[1]; o0.z = acc[2]; o0.w = acc[3];
        o1.x = acc[4]; o1.y = acc[5]; o1.z = acc[6]; o1.w = acc[7];
        ps4[0] = o0; ps4[1] = o1;
        if (FIN) {
            float4* pt4 = (float4*)&d_pt[(size_t)blockIdx.x * N + (size_t)j4 * 8];
            float4 p0, p1;
            p0.x = tac[0]; p0.y = tac[1]; p0.z = tac[2]; p0.w = tac[3];
            p1.x = tac[4]; p1.y = tac[5]; p1.z = tac[6]; p1.w = tac[7];
            pt4[0] = p0; pt4[1] = p1;
        }
    }
}

// ---------------------------------------------------------------------------
// Kernel 3: combine 256 strip partials -> v_j = NU / colsum_j.
// 8 partial-groups of 32 strips per column, 32 columns per block.
// grid 256, block 256 -> 65k threads, fully coalesced.
// ---------------------------------------------------------------------------
__global__ __launch_bounds__(256) void v_combine_kernel()
{
    __shared__ float sm[8][32];
    const int tid = threadIdx.x;
    const int cl = tid & 31;                      // column within block
    const int g = tid >> 5;                       // partial group 0..7
    const int j = blockIdx.x * 32 + cl;

    float s = 0.0f;
#pragma unroll 8
    for (int k = 0; k < 32; ++k)
        s += d_ps[(size_t)(g * 32 + k) * N + j];
    sm[g][cl] = s;
    __syncthreads();
    if (tid < 32) {
        float tot = 0.0f;
#pragma unroll
        for (int q = 0; q < 8; ++q) tot += sm[q][tid];
        d_v[blockIdx.x * 32 + tid] = NUVAL / tot;
    }
}

// Final combine: also loss = sum_j v_j * t_j.
__global__ __launch_bounds__(256) void v_combine_final_kernel(float* __restrict__ out)
{
    __shared__ float sm[8][32];
    __shared__ float smt[8][32];
    const int tid = threadIdx.x;
    const int cl = tid & 31;
    const int g = tid >> 5;
    const int j = blockIdx.x * 32 + cl;

    float s = 0.0f, t = 0.0f;
#pragma unroll 8
    for (int k = 0; k < 32; ++k) {
        s += d_ps[(size_t)(g * 32 + k) * N + j];
        t += d_pt[(size_t)(g * 32 + k) * N + j];
    }
    sm[g][cl] = s;
    smt[g][cl] = t;
    __syncthreads();
    if (tid < 32) {
        float tot = 0.0f, tt = 0.0f;
#pragma unroll
        for (int q = 0; q < 8; ++q) { tot += sm[q][tid]; tt += smt[q][tid]; }
        float lp = (NUVAL / tot) * tt;
#pragma unroll
        for (int o = 16; o > 0; o >>= 1) lp += __shfl_xor_sync(0xffffffffu, lp, o);
        if (tid == 0) atomicAdd(out, lp);
    }
}

// ---------------------------------------------------------------------------
extern "C" void kernel_launch(void* const* d_in, const int* in_sizes, int n_in,
                              void* d_out, int out_size)
{
    const float* x = (const float*)d_in[0];
    const float* y = (const float*)d_in[1];
    float* out = (float*)d_out;

    build_k_kernel<<<dim3(64, 64), 256>>>(x, y, out);

    for (int t = 0; t < 10; ++t) {
        if (t < 9) {
            sweep_kernel<false><<<NSTRIPS, 1024>>>();
            v_combine_kernel<<<N / 32, 256>>>();
        } else {
            sweep_kernel<true><<<NSTRIPS, 1024>>>();
            v_combine_final_kernel<<<N / 32, 256>>>(out);
        }
    }
}

// round 16
// speedup vs baseline: 1.2586x; 1.0231x over previous
#include <cuda_runtime.h>
#include <cuda_bf16.h>
#include <math.h>

#define N 8192
#define KD 32
#define STRIP 32
#define NSTRIPS (N / STRIP)     // 256

#define MUVAL (1.0f / 8192.0f)
#define NUVAL (1.0f / 8192.0f)

// Scratch (allocation-free: device globals)
__device__ __nv_bfloat16 d_K[(size_t)N * N];      // 128 MB: K = exp(-C) bf16
__device__ float d_v[N];                           // v = exp(g)
__device__ float d_ps[(size_t)NSTRIPS * N];        // column-sum partials (8 MB)
__device__ float d_pt[(size_t)NSTRIPS * N];        // loss partials (final iter)

__device__ __forceinline__ unsigned tf32cvt(float v)
{
    unsigned r;
    asm("cvt.rna.tf32.f32 %0, %1;" : "=r"(r) : "f"(v));
    return r;
}

__device__ __forceinline__ void mma_tf32(
    float& d0, float& d1, float& d2, float& d3,
    unsigned a0, unsigned a1, unsigned a2, unsigned a3,
    unsigned b0, unsigned b1)
{
    asm("mma.sync.aligned.m16n8k8.row.col.f32.tf32.tf32.f32 "
        "{%0,%1,%2,%3}, {%4,%5,%6,%7}, {%8,%9}, {%0,%1,%2,%3};"
        : "+f"(d0), "+f"(d1), "+f"(d2), "+f"(d3)
        : "r"(a0), "r"(a1), "r"(a2), "r"(a3), "r"(b0), "r"(b1));
}

// ---------------------------------------------------------------------------
// Kernel 1: build K = exp(-(|x_i|^2 + |y_j|^2 - 2 x_i.y_j)) in bf16 via
// tf32 tensor-core MMA. 128x128 tile per block, 8 warps.
// Also inits v = 1 and zeroes the output scalar.
// ---------------------------------------------------------------------------
__global__ __launch_bounds__(256) void build_k_kernel(
    const float* __restrict__ x, const float* __restrict__ y,
    float* __restrict__ out)
{
    __shared__ float xs[128][36];
    __shared__ float ys[128][36];
    __shared__ float xn[128];
    __shared__ float yn[128];

    const int tid = threadIdx.x;
    const int lane = tid & 31;
    const int w = tid >> 5;          // warp 0..7
    const int bx = blockIdx.x, by = blockIdx.y;
    const int row0 = by * 128, col0 = bx * 128;

    {
        int gid = (by * gridDim.x + bx) * 256 + tid;
        if (gid < N) d_v[gid] = 1.0f;
        if (gid == 0) out[0] = 0.0f;
    }

    const float4* x4 = (const float4*)(x + (size_t)row0 * KD);
    const float4* y4 = (const float4*)(y + (size_t)col0 * KD);
#pragma unroll
    for (int it = 0; it < 4; ++it) {
        int f = tid + it * 256;          // 0..1023
        int r = f >> 3;
        int c = (f & 7) * 4;
        float4 vx = x4[f];
        xs[r][c] = vx.x; xs[r][c + 1] = vx.y; xs[r][c + 2] = vx.z; xs[r][c + 3] = vx.w;
        float4 vy = y4[f];
        ys[r][c] = vy.x; ys[r][c + 1] = vy.y; ys[r][c + 2] = vy.z; ys[r][c + 3] = vy.w;
    }
    __syncthreads();

    if (tid < 128) {
        float s = 0.0f;
#pragma unroll
        for (int k = 0; k < KD; ++k) { float a = xs[tid][k]; s = fmaf(a, a, s); }
        xn[tid] = s;
    } else {
        int r = tid - 128;
        float s = 0.0f;
#pragma unroll
        for (int k = 0; k < KD; ++k) { float a = ys[r][k]; s = fmaf(a, a, s); }
        yn[r] = s;
    }
    __syncthreads();

    const int g = lane >> 2;         // 0..7
    const int tg = lane & 3;         // 0..3
    const int ra = 16 * w + g;       // A-frag row (local)
    const int rb = ra + 8;

    unsigned A[4][4];
#pragma unroll
    for (int k8 = 0; k8 < 4; ++k8) {
        A[k8][0] = tf32cvt(xs[ra][k8 * 8 + tg]);
        A[k8][1] = tf32cvt(xs[rb][k8 * 8 + tg]);
        A[k8][2] = tf32cvt(xs[ra][k8 * 8 + tg + 4]);
        A[k8][3] = tf32cvt(xs[rb][k8 * 8 + tg + 4]);
    }

    float acc[16][4];
#pragma unroll
    for (int n = 0; n < 16; ++n)
#pragma unroll
        for (int q = 0; q < 4; ++q) acc[n][q] = 0.0f;

#pragma unroll
    for (int n = 0; n < 16; ++n) {
        const int yr = n * 8 + g;
#pragma unroll
        for (int k8 = 0; k8 < 4; ++k8) {
            unsigned b0 = tf32cvt(ys[yr][k8 * 8 + tg]);
            unsigned b1 = tf32cvt(ys[yr][k8 * 8 + tg + 4]);
            mma_tf32(acc[n][0], acc[n][1], acc[n][2], acc[n][3],
                     A[k8][0], A[k8][1], A[k8][2], A[k8][3], b0, b1);
        }
    }

    const float xna = xn[ra];
    const float xnb = xn[rb];
    const int gra = row0 + ra;
    const int grb = row0 + rb;
#pragma unroll
    for (int n = 0; n < 16; ++n) {
        int c0 = n * 8 + 2 * tg;
        float yn0 = yn[c0], yn1 = yn[c0 + 1];
        float k00 = __expf(2.0f * acc[n][0] - xna - yn0);
        float k01 = __expf(2.0f * acc[n][1] - xna - yn1);
        float k10 = __expf(2.0f * acc[n][2] - xnb - yn0);
        float k11 = __expf(2.0f * acc[n][3] - xnb - yn1);
        *(__nv_bfloat162*)(d_K + (size_t)gra * N + col0 + c0) = __floats2bfloat162_rn(k00, k01);
        *(__nv_bfloat162*)(d_K + (size_t)grb * N + col0 + c0) = __floats2bfloat162_rn(k10, k11);
    }
}

// ---------------------------------------------------------------------------
// Kernel 2 (fused sweep): block owns a 32-row strip of K.
//   Phase 1 (column-major): warp (rs=w&3, cc=w>>2) owns an 8-row x 128-uint4
//     patch; v held in registers (8 floats per col-iter), row sums finished
//     with warp butterflies + smem reduce. Kills the per-row v re-stream.
//   Phase 2: ps[strip][j] = sum_i K_ij u_i (strip re-read, hits L2)
// grid NSTRIPS=256, block 1024, 1 block/SM (resident set 74 MB < L2).
// FIN: also t-partials sum_i (-log K) K u for the loss.
// ---------------------------------------------------------------------------
template <bool FIN>
__global__ __launch_bounds__(1024, 1) void sweep_kernel()
{
    __shared__ float part[STRIP][9];     // row partials per col-chunk (padded)
    __shared__ float us[STRIP];

    const int tid = threadIdx.x;
    const int wrp = tid >> 5;            // 0..31
    const int lane = tid & 31;
    const int i0 = blockIdx.x * STRIP;

    const uint4*  K8 = (const uint4*)d_K;   // 1024 uint4 per row
    const float4* v4 = (const float4*)d_v;

    // ---- Phase 1: column-major row sums ----
    {
        const int rs = wrp & 3;              // row subset: rows r0..r0+7
        const int cc = wrp >> 2;             // col chunk:  128 uint4-cols
        const int r0 = i0 + rs * 8;

        float acc[8];
#pragma unroll
        for (int r = 0; r < 8; ++r) acc[r] = 0.0f;

#pragma unroll
        for (int c = 0; c < 4; ++c) {
            const int j4 = cc * 128 + c * 32 + lane;
            float4 va = v4[2 * j4];
            float4 vb = v4[2 * j4 + 1];
#pragma unroll
            for (int r = 0; r < 8; ++r) {
                union { uint4 u; __nv_bfloat162 h[4]; } k;
                k.u = K8[(size_t)(r0 + r) * (N / 8) + j4];
                float2 p;
                float s = acc[r];
                p = __bfloat1622float2(k.h[0]); s = fmaf(p.x, va.x, s); s = fmaf(p.y, va.y, s);
                p = __bfloat1622float2(k.h[1]); s = fmaf(p.x, va.z, s); s = fmaf(p.y, va.w, s);
                p = __bfloat1622float2(k.h[2]); s = fmaf(p.x, vb.x, s); s = fmaf(p.y, vb.y, s);
                p = __bfloat1622float2(k.h[3]); s = fmaf(p.x, vb.z, s); s = fmaf(p.y, vb.w, s);
                acc[r] = s;
            }
        }

#pragma unroll
        for (int r = 0; r < 8; ++r)
#pragma unroll
            for (int o = 16; o > 0; o >>= 1)
                acc[r] += __shfl_xor_sync(0xffffffffu, acc[r], o);

        if (lane < 8) part[rs * 8 + lane][cc] = acc[lane];
    }
    __syncthreads();
    if (tid < STRIP) {
        float s = 0.0f;
#pragma unroll
        for (int q = 0; q < 8; ++q) s += part[tid][q];
        us[tid] = MUVAL / s;
    }
    __syncthreads();

    // ---- Phase 2: column partials over the strip; 1 uint4 col / thread ----
    {
        const int j4 = tid;                          // uint4 col index 0..1023
        float acc[8];
        float tac[8];
#pragma unroll
        for (int c = 0; c < 8; ++c) { acc[c] = 0.0f; tac[c] = 0.0f; }

#pragma unroll 4
        for (int r = 0; r < STRIP; ++r) {
            union { uint4 u; __nv_bfloat162 h[4]; } k;
            k.u = K8[(size_t)(i0 + r) * (N / 8) + j4];
            float ur = us[r];
            float c[8];
            float2 t0 = __bfloat1622float2(k.h[0]);
            float2 t1 = __bfloat1622float2(k.h[1]);
            float2 t2 = __bfloat1622float2(k.h[2]);
            float2 t3 = __bfloat1622float2(k.h[3]);
            c[0] = t0.x; c[1] = t0.y; c[2] = t1.x; c[3] = t1.y;
            c[4] = t2.x; c[5] = t2.y; c[6] = t3.x; c[7] = t3.y;
#pragma unroll
            for (int j = 0; j < 8; ++j) {
                acc[j] = fmaf(c[j], ur, acc[j]);
                if (FIN) {
                    float kj = c[j];
                    tac[j] += (kj > 0.0f) ? (-__logf(kj)) * kj * ur : 0.0f;
                }
            }
        }

        float4* ps4 = (float4*)&d_ps[(size_t)blockIdx.x * N + (size_t)j4 * 8];
        float4 o0, o1;
        o0.x = acc[0]; o0.y = acc[1]; o0.z = acc[2]; o0.w = acc[3];
        o1.x = acc[4]; o1.y = acc[5]; o1.z = acc[6]; o1.w = acc[7];
        ps4[0] = o0; ps4[1] = o1;
        if (FIN) {
            float4* pt4 = (float4*)&d_pt[(size_t)blockIdx.x * N + (size_t)j4 * 8];
            float4 p0, p1;
            p0.x = tac[0]; p0.y = tac[1]; p0.z = tac[2]; p0.w = tac[3];
            p1.x = tac[4]; p1.y = tac[5]; p1.z = tac[6]; p1.w = tac[7];
            pt4[0] = p0; pt4[1] = p1;
        }
    }
}

// ---------------------------------------------------------------------------
// Kernel 3: combine 256 strip partials -> v_j = NU / colsum_j.
// 8 partial-groups of 32 strips per column, 32 columns per block.
// grid 256, block 256 -> 65k threads, fully coalesced.
// ---------------------------------------------------------------------------
__global__ __launch_bounds__(256) void v_combine_kernel()
{
    __shared__ float sm[8][32];
    const int tid = threadIdx.x;
    const int cl = tid & 31;                      // column within block
    const int g = tid >> 5;                       // partial group 0..7
    const int j = blockIdx.x * 32 + cl;

    float s = 0.0f;
#pragma unroll 8
    for (int k = 0; k < 32; ++k)
        s += d_ps[(size_t)(g * 32 + k) * N + j];
    sm[g][cl] = s;
    __syncthreads();
    if (tid < 32) {
        float tot = 0.0f;
#pragma unroll
        for (int q = 0; q < 8; ++q) tot += sm[q][tid];
        d_v[blockIdx.x * 32 + tid] = NUVAL / tot;
    }
}

// Final combine: also loss = sum_j v_j * t_j.
__global__ __launch_bounds__(256) void v_combine_final_kernel(float* __restrict__ out)
{
    __shared__ float sm[8][32];
    __shared__ float smt[8][32];
    const int tid = threadIdx.x;
    const int cl = tid & 31;
    const int g = tid >> 5;
    const int j = blockIdx.x * 32 + cl;

    float s = 0.0f, t = 0.0f;
#pragma unroll 8
    for (int k = 0; k < 32; ++k) {
        s += d_ps[(size_t)(g * 32 + k) * N + j];
        t += d_pt[(size_t)(g * 32 + k) * N + j];
    }
    sm[g][cl] = s;
    smt[g][cl] = t;
    __syncthreads();
    if (tid < 32) {
        float tot = 0.0f, tt = 0.0f;
#pragma unroll
        for (int q = 0; q < 8; ++q) { tot += sm[q][tid]; tt += smt[q][tid]; }
        float lp = (NUVAL / tot) * tt;
#pragma unroll
        for (int o = 16; o > 0; o >>= 1) lp += __shfl_xor_sync(0xffffffffu, lp, o);
        if (tid == 0) atomicAdd(out, lp);
    }
}

// ---------------------------------------------------------------------------
extern "C" void kernel_launch(void* const* d_in, const int* in_sizes, int n_in,
                              void* d_out, int out_size)
{
    const float* x = (const float*)d_in[0];
    const float* y = (const float*)d_in[1];
    float* out = (float*)d_out;

    build_k_kernel<<<dim3(64, 64), 256>>>(x, y, out);

    for (int t = 0; t < 10; ++t) {
        if (t < 9) {
            sweep_kernel<false><<<NSTRIPS, 1024>>>();
            v_combine_kernel<<<N / 32, 256>>>();
        } else {
            sweep_kernel<true><<<NSTRIPS, 1024>>>();
            v_combine_final_kernel<<<N / 32, 256>>>(out);
        }
    }
}